// round 8
// baseline (speedup 1.0000x reference)
#include <cuda_runtime.h>

#define Ncst 8
#define Scst 2
#define Lcst 512
#define Ecst 1024
#define Hcst 16
#define Dcst 64
#define Bcst 16           // N*S
#define BHcst 256         // B*H
#define Tcst 8192         // B*L tokens

// Scratch (device globals: allocation-free inside kernel_launch)
__device__ float g_qp[BHcst * Lcst * Dcst];                 // [bh][l][d]
__device__ float g_kp[BHcst * Lcst * Dcst];
__device__ float g_vp[BHcst * Lcst * Dcst];
__device__ float g_st[(size_t)BHcst * Lcst * Lcst];         // S^T: [bh][k][q]  (256 MB)
__device__ float g_cm[BHcst * Lcst];                        // per-(bh,k) column max over q
__device__ float g_ci[BHcst * Lcst];                        // per-(bh,k) 1/sum
__device__ float g_att[(size_t)Tcst * Ecst];                // attention out [t][e]

// ---------------------------------------------------------------------------
// Kernel 1: per-head 64x64 projections.  out[l][d] = sum_j x[l][j] * W[d][j]
// grid (BH, 3), block 256. Thread computes 4 consecutive d for one row.
// ---------------------------------------------------------------------------
__global__ __launch_bounds__(256) void proj_kernel(
    const float* __restrict__ vals, const float* __restrict__ keys,
    const float* __restrict__ qry,
    const float* __restrict__ Wv, const float* __restrict__ Wk,
    const float* __restrict__ Wq)
{
    const int which = blockIdx.y;
    const float* x = (which == 0) ? vals : (which == 1) ? keys : qry;
    const float* W = (which == 0) ? Wv : (which == 1) ? Wk : Wq;
    float* out = (which == 0) ? g_vp : (which == 1) ? g_kp : g_qp;

    const int bh = blockIdx.x;
    const int b = bh >> 4, h = bh & 15;

    __shared__ float Ws[Dcst][Dcst];   // Ws[j][d] = W[d][j]  (float4 over d)
    __shared__ float Xs[16][Dcst];

    const int tid = threadIdx.x;
    for (int i = tid; i < Dcst * Dcst; i += 256) {
        int d = i >> 6, j = i & 63;
        Ws[j][d] = W[i];
    }
    __syncthreads();

    const int d4 = tid & 15;       // handles d = d4*4 .. d4*4+3
    const int r  = tid >> 4;       // row within 16-row chunk
    const size_t xbase = (size_t)b * Lcst * Ecst + (size_t)h * Dcst;

    for (int l0 = 0; l0 < Lcst; l0 += 16) {
        *(float4*)&Xs[r][d4 * 4] =
            *(const float4*)&x[xbase + (size_t)(l0 + r) * Ecst + d4 * 4];
        __syncthreads();

        float4 acc = make_float4(0.f, 0.f, 0.f, 0.f);
#pragma unroll
        for (int j = 0; j < Dcst; j++) {
            float xv = Xs[r][j];
            float4 w = *(const float4*)&Ws[j][d4 * 4];
            acc.x += xv * w.x; acc.y += xv * w.y;
            acc.z += xv * w.z; acc.w += xv * w.w;
        }
        *(float4*)&out[((size_t)bh * Lcst + l0 + r) * Dcst + d4 * 4] = acc;
        __syncthreads();
    }
}

// ---------------------------------------------------------------------------
// Kernel 2: S^T[bh][k][q] = (K[k] . Q[q]) * 1/sqrt(512), masked on q.
// 128x128 tile, BK=32, 8x8 micro-tile, 256 threads. grid (4,4,256).
// ---------------------------------------------------------------------------
__global__ __launch_bounds__(256) void qk_kernel(const int* __restrict__ mask)
{
    const int bh = blockIdx.z;
    const int b = bh >> 4;
    const int k0 = blockIdx.y * 128;   // key rows (M)
    const int q0 = blockIdx.x * 128;   // query cols (N)

    __shared__ float As[32][132];      // As[j][k-row]
    __shared__ float Bs[32][132];      // Bs[j][q-col]
    __shared__ float Mf[128];          // mask flag per q (1=keep, 0=mask)

    const int tid = threadIdx.x;
    const int tx = tid & 15, ty = tid >> 4;

    if (tid < 128) Mf[tid] = (mask[b * Lcst + q0 + tid] == 0) ? 0.f : 1.f;

    float c[8][8];
#pragma unroll
    for (int i = 0; i < 8; i++)
#pragma unroll
        for (int j = 0; j < 8; j++) c[i][j] = 0.f;

    const float* kbase = &g_kp[(size_t)bh * Lcst * Dcst];
    const float* qbase = &g_qp[(size_t)bh * Lcst * Dcst];

    for (int kk0 = 0; kk0 < Dcst; kk0 += 32) {
#pragma unroll
        for (int it = 0; it < 4; it++) {
            int idx = tid + it * 256;          // 1024 float4s (128 rows x 8)
            int row = idx >> 3, c4 = idx & 7;
            float4 va = *(const float4*)&kbase[(size_t)(k0 + row) * Dcst + kk0 + c4 * 4];
            As[c4 * 4 + 0][row] = va.x; As[c4 * 4 + 1][row] = va.y;
            As[c4 * 4 + 2][row] = va.z; As[c4 * 4 + 3][row] = va.w;
            float4 vb = *(const float4*)&qbase[(size_t)(q0 + row) * Dcst + kk0 + c4 * 4];
            Bs[c4 * 4 + 0][row] = vb.x; Bs[c4 * 4 + 1][row] = vb.y;
            Bs[c4 * 4 + 2][row] = vb.z; Bs[c4 * 4 + 3][row] = vb.w;
        }
        __syncthreads();
#pragma unroll
        for (int kj = 0; kj < 32; kj++) {
            float a[8], bb[8];
            *(float4*)&a[0] = *(const float4*)&As[kj][ty * 8];
            *(float4*)&a[4] = *(const float4*)&As[kj][ty * 8 + 4];
            *(float4*)&bb[0] = *(const float4*)&Bs[kj][tx * 8];
            *(float4*)&bb[4] = *(const float4*)&Bs[kj][tx * 8 + 4];
#pragma unroll
            for (int i = 0; i < 8; i++)
#pragma unroll
                for (int j = 0; j < 8; j++) c[i][j] += a[i] * bb[j];
        }
        __syncthreads();
    }

    const float scale = 0.044194173824159216f;   // 1/sqrt(512)
    const size_t base = (size_t)bh * Lcst * Lcst;
#pragma unroll
    for (int i = 0; i < 8; i++) {
        int kr = k0 + ty * 8 + i;
#pragma unroll
        for (int j4 = 0; j4 < 2; j4++) {
            int qj = tx * 8 + j4 * 4;
            float4 r;
            r.x = (Mf[qj + 0] == 0.f) ? -1e30f : c[i][j4 * 4 + 0] * scale;
            r.y = (Mf[qj + 1] == 0.f) ? -1e30f : c[i][j4 * 4 + 1] * scale;
            r.z = (Mf[qj + 2] == 0.f) ? -1e30f : c[i][j4 * 4 + 2] * scale;
            r.w = (Mf[qj + 3] == 0.f) ? -1e30f : c[i][j4 * 4 + 3] * scale;
            *(float4*)&g_st[base + (size_t)kr * Lcst + q0 + qj] = r;
        }
    }
}

// ---------------------------------------------------------------------------
// Kernel 3: per (bh,k) row of S^T, reduce over the 512 q values: max, 1/sum.
// One warp per row. grid 16384, block 256 (8 warps).
// ---------------------------------------------------------------------------
__global__ __launch_bounds__(256) void colstat_kernel()
{
    const int gw = blockIdx.x * 8 + (threadIdx.x >> 5);   // flattened (bh*512 + k)
    const int lane = threadIdx.x & 31;
    const float* row = &g_st[(size_t)gw * Lcst];

    float4 v[4];
    float m = -1e38f;
#pragma unroll
    for (int i = 0; i < 4; i++) {
        v[i] = *(const float4*)&row[(i * 32 + lane) * 4];
        m = fmaxf(m, fmaxf(fmaxf(v[i].x, v[i].y), fmaxf(v[i].z, v[i].w)));
    }
#pragma unroll
    for (int o = 16; o > 0; o >>= 1) m = fmaxf(m, __shfl_xor_sync(0xffffffffu, m, o));

    float s = 0.f;
#pragma unroll
    for (int i = 0; i < 4; i++) {
        s += __expf(v[i].x - m) + __expf(v[i].y - m) +
             __expf(v[i].z - m) + __expf(v[i].w - m);
    }
#pragma unroll
    for (int o = 16; o > 0; o >>= 1) s += __shfl_xor_sync(0xffffffffu, s, o);

    if (lane == 0) { g_cm[gw] = m; g_ci[gw] = 1.f / s; }
}

// ---------------------------------------------------------------------------
// Kernel 4: Out[q][d] = sum_k exp(S^T[k][q]-m[k])*invZ[k] * V[k][d]
// exp fused into the P-tile load. 128(q) x 64(d) tile, BK=32, 8x4 micro.
// grid (4, 256), block 256.
// ---------------------------------------------------------------------------
__global__ __launch_bounds__(256) void av_kernel()
{
    const int bh = blockIdx.y;
    const int b = bh >> 4, h = bh & 15;
    const int q0 = blockIdx.x * 128;

    __shared__ float Ps[32][132];   // Ps[kj][q]
    __shared__ float Vs[32][68];    // Vs[kj][d]

    const int tid = threadIdx.x;
    const int tx = tid & 15, ty = tid >> 4;

    float c[8][4];
#pragma unroll
    for (int i = 0; i < 8; i++)
#pragma unroll
        for (int j = 0; j < 4; j++) c[i][j] = 0.f;

    const float* stbase = &g_st[(size_t)bh * Lcst * Lcst];
    const float* vbase  = &g_vp[(size_t)bh * Lcst * Dcst];

    for (int kc = 0; kc < Lcst; kc += 32) {
#pragma unroll
        for (int it = 0; it < 4; it++) {
            int idx = tid + it * 256;            // 1024 float4s (32 rows x 32)
            int kr = idx >> 5, q4 = idx & 31;
            int kg = kc + kr;
            float mv = g_cm[bh * Lcst + kg];
            float iz = g_ci[bh * Lcst + kg];
            float4 v = *(const float4*)&stbase[(size_t)kg * Lcst + q0 + q4 * 4];
            float4 p;
            p.x = __expf(v.x - mv) * iz;
            p.y = __expf(v.y - mv) * iz;
            p.z = __expf(v.z - mv) * iz;
            p.w = __expf(v.w - mv) * iz;
            *(float4*)&Ps[kr][q4 * 4] = p;
        }
#pragma unroll
        for (int it = 0; it < 2; it++) {
            int idx = tid + it * 256;            // 512 float4s (32 rows x 16)
            int kr = idx >> 4, d4 = idx & 15;
            *(float4*)&Vs[kr][d4 * 4] =
                *(const float4*)&vbase[(size_t)(kc + kr) * Dcst + d4 * 4];
        }
        __syncthreads();
#pragma unroll
        for (int kj = 0; kj < 32; kj++) {
            float a[8], bb[4];
            *(float4*)&a[0] = *(const float4*)&Ps[kj][ty * 8];
            *(float4*)&a[4] = *(const float4*)&Ps[kj][ty * 8 + 4];
            *(float4*)&bb[0] = *(const float4*)&Vs[kj][tx * 4];
#pragma unroll
            for (int i = 0; i < 8; i++)
#pragma unroll
                for (int j = 0; j < 4; j++) c[i][j] += a[i] * bb[j];
        }
        __syncthreads();
    }

#pragma unroll
    for (int i = 0; i < 8; i++) {
        int q = q0 + ty * 8 + i;
        *(float4*)&g_att[((size_t)(b * Lcst + q)) * Ecst + h * Dcst + tx * 4] =
            make_float4(c[i][0], c[i][1], c[i][2], c[i][3]);
    }
}

// ---------------------------------------------------------------------------
// Kernel 5: out[t][i] = sum_j g_att[t][j] * Wo[i][j] + bo[i]
// 128x128x16 tiles, 8x8 micro. grid (64, 8), block 256.
// ---------------------------------------------------------------------------
__global__ __launch_bounds__(256) void out_gemm(const float* __restrict__ Wo,
                                                const float* __restrict__ bo,
                                                float* __restrict__ out)
{
    const int m0 = blockIdx.x * 128;
    const int n0 = blockIdx.y * 128;

    __shared__ float As[16][132];
    __shared__ float Bs[16][132];

    const int tid = threadIdx.x;
    const int tx = tid & 15, ty = tid >> 4;

    float c[8][8];
#pragma unroll
    for (int i = 0; i < 8; i++)
#pragma unroll
        for (int j = 0; j < 8; j++) c[i][j] = 0.f;

    for (int k0 = 0; k0 < Ecst; k0 += 16) {
#pragma unroll
        for (int it = 0; it < 2; it++) {
            int idx = tid + it * 256;        // 512 float4s (128 rows x 4)
            int row = idx >> 2, c4 = idx & 3;
            float4 va = *(const float4*)&g_att[(size_t)(m0 + row) * Ecst + k0 + c4 * 4];
            As[c4 * 4 + 0][row] = va.x; As[c4 * 4 + 1][row] = va.y;
            As[c4 * 4 + 2][row] = va.z; As[c4 * 4 + 3][row] = va.w;
            float4 vb = *(const float4*)&Wo[(size_t)(n0 + row) * Ecst + k0 + c4 * 4];
            Bs[c4 * 4 + 0][row] = vb.x; Bs[c4 * 4 + 1][row] = vb.y;
            Bs[c4 * 4 + 2][row] = vb.z; Bs[c4 * 4 + 3][row] = vb.w;
        }
        __syncthreads();
#pragma unroll
        for (int kj = 0; kj < 16; kj++) {
            float a[8], bb[8];
            *(float4*)&a[0] = *(const float4*)&As[kj][ty * 8];
            *(float4*)&a[4] = *(const float4*)&As[kj][ty * 8 + 4];
            *(float4*)&bb[0] = *(const float4*)&Bs[kj][tx * 8];
            *(float4*)&bb[4] = *(const float4*)&Bs[kj][tx * 8 + 4];
#pragma unroll
            for (int i = 0; i < 8; i++)
#pragma unroll
                for (int j = 0; j < 8; j++) c[i][j] += a[i] * bb[j];
        }
        __syncthreads();
    }

#pragma unroll
    for (int i = 0; i < 8; i++) {
        int m = m0 + ty * 8 + i;
#pragma unroll
        for (int j4 = 0; j4 < 2; j4++) {
            int n = n0 + tx * 8 + j4 * 4;
            float4 r;
            r.x = c[i][j4 * 4 + 0] + bo[n + 0];
            r.y = c[i][j4 * 4 + 1] + bo[n + 1];
            r.z = c[i][j4 * 4 + 2] + bo[n + 2];
            r.w = c[i][j4 * 4 + 3] + bo[n + 3];
            *(float4*)&out[(size_t)m * Ecst + n] = r;
        }
    }
}

// ---------------------------------------------------------------------------
extern "C" void kernel_launch(void* const* d_in, const int* in_sizes, int n_in,
                              void* d_out, int out_size)
{
    const float* vals = (const float*)d_in[0];
    const float* keys = (const float*)d_in[1];
    const float* qry  = (const float*)d_in[2];
    const int*   mask = (const int*)d_in[3];
    const float* Wv   = (const float*)d_in[4];
    const float* Wk   = (const float*)d_in[5];
    const float* Wq   = (const float*)d_in[6];
    const float* Wo   = (const float*)d_in[7];
    const float* bo   = (const float*)d_in[8];
    float* out = (float*)d_out;

    proj_kernel<<<dim3(BHcst, 3), 256>>>(vals, keys, qry, Wv, Wk, Wq);
    qk_kernel<<<dim3(4, 4, BHcst), 256>>>(mask);
    colstat_kernel<<<BHcst * Lcst / 8, 256>>>();
    av_kernel<<<dim3(4, BHcst), 256>>>();
    out_gemm<<<dim3(Tcst / 128, Ecst / 128), 256>>>(Wo, bo, out);
}

// round 9
// speedup vs baseline: 1.0012x; 1.0012x over previous
#include <cuda_runtime.h>

#define Ncst 8
#define Scst 2
#define Lcst 512
#define Ecst 1024
#define Hcst 16
#define Dcst 64
#define Bcst 16           // N*S
#define BHcst 256         // B*H
#define Tcst 8192         // B*L tokens

// Scratch (device globals: allocation-free inside kernel_launch)
__device__ float g_qp[BHcst * Lcst * Dcst];                 // [bh][l][d]
__device__ float g_kp[BHcst * Lcst * Dcst];
__device__ float g_vp[BHcst * Lcst * Dcst];
__device__ float g_st[(size_t)BHcst * Lcst * Lcst];         // S^T: [bh][k][q]  (256 MB)
__device__ float g_cm[BHcst * Lcst];                        // per-(bh,k) column max over q
__device__ float g_ci[BHcst * Lcst];                        // per-(bh,k) 1/sum
__device__ float g_att[(size_t)Tcst * Ecst];                // attention out [t][e]

// ---------------------------------------------------------------------------
// Kernel 1: per-head 64x64 projections.  out[l][d] = sum_j x[l][j] * W[d][j]
// grid (BH, 3), block 256. Thread computes 4 consecutive d for one row.
// ---------------------------------------------------------------------------
__global__ __launch_bounds__(256) void proj_kernel(
    const float* __restrict__ vals, const float* __restrict__ keys,
    const float* __restrict__ qry,
    const float* __restrict__ Wv, const float* __restrict__ Wk,
    const float* __restrict__ Wq)
{
    const int which = blockIdx.y;
    const float* x = (which == 0) ? vals : (which == 1) ? keys : qry;
    const float* W = (which == 0) ? Wv : (which == 1) ? Wk : Wq;
    float* out = (which == 0) ? g_vp : (which == 1) ? g_kp : g_qp;

    const int bh = blockIdx.x;
    const int b = bh >> 4, h = bh & 15;

    __shared__ float Ws[Dcst][Dcst];   // Ws[j][d] = W[d][j]  (float4 over d)
    __shared__ float Xs[16][Dcst];

    const int tid = threadIdx.x;
    for (int i = tid; i < Dcst * Dcst; i += 256) {
        int d = i >> 6, j = i & 63;
        Ws[j][d] = W[i];
    }
    __syncthreads();

    const int d4 = tid & 15;       // handles d = d4*4 .. d4*4+3
    const int r  = tid >> 4;       // row within 16-row chunk
    const size_t xbase = (size_t)b * Lcst * Ecst + (size_t)h * Dcst;

    for (int l0 = 0; l0 < Lcst; l0 += 16) {
        *(float4*)&Xs[r][d4 * 4] =
            *(const float4*)&x[xbase + (size_t)(l0 + r) * Ecst + d4 * 4];
        __syncthreads();

        float4 acc = make_float4(0.f, 0.f, 0.f, 0.f);
#pragma unroll
        for (int j = 0; j < Dcst; j++) {
            float xv = Xs[r][j];
            float4 w = *(const float4*)&Ws[j][d4 * 4];
            acc.x += xv * w.x; acc.y += xv * w.y;
            acc.z += xv * w.z; acc.w += xv * w.w;
        }
        *(float4*)&out[((size_t)bh * Lcst + l0 + r) * Dcst + d4 * 4] = acc;
        __syncthreads();
    }
}

// ---------------------------------------------------------------------------
// Kernel 2: S^T[bh][k][q] = (K[k] . Q[q]) * 1/sqrt(512), masked on q.
// 128x128 tile, BK=32, 8x8 micro-tile, 256 threads. grid (4,4,256).
// ---------------------------------------------------------------------------
__global__ __launch_bounds__(256) void qk_kernel(const int* __restrict__ mask)
{
    const int bh = blockIdx.z;
    const int b = bh >> 4;
    const int k0 = blockIdx.y * 128;   // key rows (M)
    const int q0 = blockIdx.x * 128;   // query cols (N)

    __shared__ float As[32][132];      // As[j][k-row]
    __shared__ float Bs[32][132];      // Bs[j][q-col]
    __shared__ float Mf[128];          // mask flag per q (1=keep, 0=mask)

    const int tid = threadIdx.x;
    const int tx = tid & 15, ty = tid >> 4;

    if (tid < 128) Mf[tid] = (mask[b * Lcst + q0 + tid] == 0) ? 0.f : 1.f;

    float c[8][8];
#pragma unroll
    for (int i = 0; i < 8; i++)
#pragma unroll
        for (int j = 0; j < 8; j++) c[i][j] = 0.f;

    const float* kbase = &g_kp[(size_t)bh * Lcst * Dcst];
    const float* qbase = &g_qp[(size_t)bh * Lcst * Dcst];

    for (int kk0 = 0; kk0 < Dcst; kk0 += 32) {
#pragma unroll
        for (int it = 0; it < 4; it++) {
            int idx = tid + it * 256;          // 1024 float4s (128 rows x 8)
            int row = idx >> 3, c4 = idx & 7;
            float4 va = *(const float4*)&kbase[(size_t)(k0 + row) * Dcst + kk0 + c4 * 4];
            As[c4 * 4 + 0][row] = va.x; As[c4 * 4 + 1][row] = va.y;
            As[c4 * 4 + 2][row] = va.z; As[c4 * 4 + 3][row] = va.w;
            float4 vb = *(const float4*)&qbase[(size_t)(q0 + row) * Dcst + kk0 + c4 * 4];
            Bs[c4 * 4 + 0][row] = vb.x; Bs[c4 * 4 + 1][row] = vb.y;
            Bs[c4 * 4 + 2][row] = vb.z; Bs[c4 * 4 + 3][row] = vb.w;
        }
        __syncthreads();
#pragma unroll
        for (int kj = 0; kj < 32; kj++) {
            float a[8], bb[8];
            *(float4*)&a[0] = *(const float4*)&As[kj][ty * 8];
            *(float4*)&a[4] = *(const float4*)&As[kj][ty * 8 + 4];
            *(float4*)&bb[0] = *(const float4*)&Bs[kj][tx * 8];
            *(float4*)&bb[4] = *(const float4*)&Bs[kj][tx * 8 + 4];
#pragma unroll
            for (int i = 0; i < 8; i++)
#pragma unroll
                for (int j = 0; j < 8; j++) c[i][j] += a[i] * bb[j];
        }
        __syncthreads();
    }

    const float scale = 0.044194173824159216f;   // 1/sqrt(512)
    const size_t base = (size_t)bh * Lcst * Lcst;
#pragma unroll
    for (int i = 0; i < 8; i++) {
        int kr = k0 + ty * 8 + i;
#pragma unroll
        for (int j4 = 0; j4 < 2; j4++) {
            int qj = tx * 8 + j4 * 4;
            float4 r;
            r.x = (Mf[qj + 0] == 0.f) ? -1e30f : c[i][j4 * 4 + 0] * scale;
            r.y = (Mf[qj + 1] == 0.f) ? -1e30f : c[i][j4 * 4 + 1] * scale;
            r.z = (Mf[qj + 2] == 0.f) ? -1e30f : c[i][j4 * 4 + 2] * scale;
            r.w = (Mf[qj + 3] == 0.f) ? -1e30f : c[i][j4 * 4 + 3] * scale;
            *(float4*)&g_st[base + (size_t)kr * Lcst + q0 + qj] = r;
        }
    }
}

// ---------------------------------------------------------------------------
// Kernel 3: per (bh,k) row of S^T, reduce over the 512 q values: max, 1/sum.
// One warp per row. grid 16384, block 256 (8 warps).
// ---------------------------------------------------------------------------
__global__ __launch_bounds__(256) void colstat_kernel()
{
    const int gw = blockIdx.x * 8 + (threadIdx.x >> 5);   // flattened (bh*512 + k)
    const int lane = threadIdx.x & 31;
    const float* row = &g_st[(size_t)gw * Lcst];

    float4 v[4];
    float m = -1e38f;
#pragma unroll
    for (int i = 0; i < 4; i++) {
        v[i] = *(const float4*)&row[(i * 32 + lane) * 4];
        m = fmaxf(m, fmaxf(fmaxf(v[i].x, v[i].y), fmaxf(v[i].z, v[i].w)));
    }
#pragma unroll
    for (int o = 16; o > 0; o >>= 1) m = fmaxf(m, __shfl_xor_sync(0xffffffffu, m, o));

    float s = 0.f;
#pragma unroll
    for (int i = 0; i < 4; i++) {
        s += __expf(v[i].x - m) + __expf(v[i].y - m) +
             __expf(v[i].z - m) + __expf(v[i].w - m);
    }
#pragma unroll
    for (int o = 16; o > 0; o >>= 1) s += __shfl_xor_sync(0xffffffffu, s, o);

    if (lane == 0) { g_cm[gw] = m; g_ci[gw] = 1.f / s; }
}

// ---------------------------------------------------------------------------
// Kernel 4: Out[q][d] = sum_k exp(S^T[k][q]-m[k])*invZ[k] * V[k][d]
// exp fused into the P-tile load. 128(q) x 64(d) tile, BK=32, 8x4 micro.
// grid (4, 256), block 256.
// ---------------------------------------------------------------------------
__global__ __launch_bounds__(256) void av_kernel()
{
    const int bh = blockIdx.y;
    const int b = bh >> 4, h = bh & 15;
    const int q0 = blockIdx.x * 128;

    __shared__ float Ps[32][132];   // Ps[kj][q]
    __shared__ float Vs[32][68];    // Vs[kj][d]

    const int tid = threadIdx.x;
    const int tx = tid & 15, ty = tid >> 4;

    float c[8][4];
#pragma unroll
    for (int i = 0; i < 8; i++)
#pragma unroll
        for (int j = 0; j < 4; j++) c[i][j] = 0.f;

    const float* stbase = &g_st[(size_t)bh * Lcst * Lcst];
    const float* vbase  = &g_vp[(size_t)bh * Lcst * Dcst];

    for (int kc = 0; kc < Lcst; kc += 32) {
#pragma unroll
        for (int it = 0; it < 4; it++) {
            int idx = tid + it * 256;            // 1024 float4s (32 rows x 32)
            int kr = idx >> 5, q4 = idx & 31;
            int kg = kc + kr;
            float mv = g_cm[bh * Lcst + kg];
            float iz = g_ci[bh * Lcst + kg];
            float4 v = *(const float4*)&stbase[(size_t)kg * Lcst + q0 + q4 * 4];
            float4 p;
            p.x = __expf(v.x - mv) * iz;
            p.y = __expf(v.y - mv) * iz;
            p.z = __expf(v.z - mv) * iz;
            p.w = __expf(v.w - mv) * iz;
            *(float4*)&Ps[kr][q4 * 4] = p;
        }
#pragma unroll
        for (int it = 0; it < 2; it++) {
            int idx = tid + it * 256;            // 512 float4s (32 rows x 16)
            int kr = idx >> 4, d4 = idx & 15;
            *(float4*)&Vs[kr][d4 * 4] =
                *(const float4*)&vbase[(size_t)(kc + kr) * Dcst + d4 * 4];
        }
        __syncthreads();
#pragma unroll
        for (int kj = 0; kj < 32; kj++) {
            float a[8], bb[4];
            *(float4*)&a[0] = *(const float4*)&Ps[kj][ty * 8];
            *(float4*)&a[4] = *(const float4*)&Ps[kj][ty * 8 + 4];
            *(float4*)&bb[0] = *(const float4*)&Vs[kj][tx * 4];
#pragma unroll
            for (int i = 0; i < 8; i++)
#pragma unroll
                for (int j = 0; j < 4; j++) c[i][j] += a[i] * bb[j];
        }
        __syncthreads();
    }

#pragma unroll
    for (int i = 0; i < 8; i++) {
        int q = q0 + ty * 8 + i;
        *(float4*)&g_att[((size_t)(b * Lcst + q)) * Ecst + h * Dcst + tx * 4] =
            make_float4(c[i][0], c[i][1], c[i][2], c[i][3]);
    }
}

// ---------------------------------------------------------------------------
// Kernel 5: out[t][i] = sum_j g_att[t][j] * Wo[i][j] + bo[i]
// 128x128x16 tiles, 8x8 micro. grid (64, 8), block 256.
// ---------------------------------------------------------------------------
__global__ __launch_bounds__(256) void out_gemm(const float* __restrict__ Wo,
                                                const float* __restrict__ bo,
                                                float* __restrict__ out)
{
    const int m0 = blockIdx.x * 128;
    const int n0 = blockIdx.y * 128;

    __shared__ float As[16][132];
    __shared__ float Bs[16][132];

    const int tid = threadIdx.x;
    const int tx = tid & 15, ty = tid >> 4;

    float c[8][8];
#pragma unroll
    for (int i = 0; i < 8; i++)
#pragma unroll
        for (int j = 0; j < 8; j++) c[i][j] = 0.f;

    for (int k0 = 0; k0 < Ecst; k0 += 16) {
#pragma unroll
        for (int it = 0; it < 2; it++) {
            int idx = tid + it * 256;        // 512 float4s (128 rows x 4)
            int row = idx >> 2, c4 = idx & 3;
            float4 va = *(const float4*)&g_att[(size_t)(m0 + row) * Ecst + k0 + c4 * 4];
            As[c4 * 4 + 0][row] = va.x; As[c4 * 4 + 1][row] = va.y;
            As[c4 * 4 + 2][row] = va.z; As[c4 * 4 + 3][row] = va.w;
            float4 vb = *(const float4*)&Wo[(size_t)(n0 + row) * Ecst + k0 + c4 * 4];
            Bs[c4 * 4 + 0][row] = vb.x; Bs[c4 * 4 + 1][row] = vb.y;
            Bs[c4 * 4 + 2][row] = vb.z; Bs[c4 * 4 + 3][row] = vb.w;
        }
        __syncthreads();
#pragma unroll
        for (int kj = 0; kj < 16; kj++) {
            float a[8], bb[8];
            *(float4*)&a[0] = *(const float4*)&As[kj][ty * 8];
            *(float4*)&a[4] = *(const float4*)&As[kj][ty * 8 + 4];
            *(float4*)&bb[0] = *(const float4*)&Bs[kj][tx * 8];
            *(float4*)&bb[4] = *(const float4*)&Bs[kj][tx * 8 + 4];
#pragma unroll
            for (int i = 0; i < 8; i++)
#pragma unroll
                for (int j = 0; j < 8; j++) c[i][j] += a[i] * bb[j];
        }
        __syncthreads();
    }

#pragma unroll
    for (int i = 0; i < 8; i++) {
        int m = m0 + ty * 8 + i;
#pragma unroll
        for (int j4 = 0; j4 < 2; j4++) {
            int n = n0 + tx * 8 + j4 * 4;
            float4 r;
            r.x = c[i][j4 * 4 + 0] + bo[n + 0];
            r.y = c[i][j4 * 4 + 1] + bo[n + 1];
            r.z = c[i][j4 * 4 + 2] + bo[n + 2];
            r.w = c[i][j4 * 4 + 3] + bo[n + 3];
            *(float4*)&out[(size_t)m * Ecst + n] = r;
        }
    }
}

// ---------------------------------------------------------------------------
extern "C" void kernel_launch(void* const* d_in, const int* in_sizes, int n_in,
                              void* d_out, int out_size)
{
    const float* vals = (const float*)d_in[0];
    const float* keys = (const float*)d_in[1];
    const float* qry  = (const float*)d_in[2];
    const int*   mask = (const int*)d_in[3];
    const float* Wv   = (const float*)d_in[4];
    const float* Wk   = (const float*)d_in[5];
    const float* Wq   = (const float*)d_in[6];
    const float* Wo   = (const float*)d_in[7];
    const float* bo   = (const float*)d_in[8];
    float* out = (float*)d_out;

    proj_kernel<<<dim3(BHcst, 3), 256>>>(vals, keys, qry, Wv, Wk, Wq);
    qk_kernel<<<dim3(4, 4, BHcst), 256>>>(mask);
    colstat_kernel<<<BHcst * Lcst / 8, 256>>>();
    av_kernel<<<dim3(4, BHcst), 256>>>();
    out_gemm<<<dim3(Tcst / 128, Ecst / 128), 256>>>(Wo, bo, out);
}

// round 10
// speedup vs baseline: 1.0016x; 1.0003x over previous
#include <cuda_runtime.h>

#define Ncst 8
#define Scst 2
#define Lcst 512
#define Ecst 1024
#define Hcst 16
#define Dcst 64
#define Bcst 16           // N*S
#define BHcst 256         // B*H
#define Tcst 8192         // B*L tokens

// Scratch (device globals: allocation-free inside kernel_launch)
__device__ float g_qp[BHcst * Lcst * Dcst];                 // [bh][l][d]
__device__ float g_kp[BHcst * Lcst * Dcst];
__device__ float g_vp[BHcst * Lcst * Dcst];
__device__ float g_st[(size_t)BHcst * Lcst * Lcst];         // S^T: [bh][k][q]  (256 MB)
__device__ float g_cm[BHcst * Lcst];                        // per-(bh,k) column max over q
__device__ float g_ci[BHcst * Lcst];                        // per-(bh,k) 1/sum
__device__ float g_att[(size_t)Tcst * Ecst];                // attention out [t][e]

// ---------------------------------------------------------------------------
// Kernel 1: per-head 64x64 projections.  out[l][d] = sum_j x[l][j] * W[d][j]
// grid (BH, 3), block 256. Thread computes 4 consecutive d for one row.
// ---------------------------------------------------------------------------
__global__ __launch_bounds__(256) void proj_kernel(
    const float* __restrict__ vals, const float* __restrict__ keys,
    const float* __restrict__ qry,
    const float* __restrict__ Wv, const float* __restrict__ Wk,
    const float* __restrict__ Wq)
{
    const int which = blockIdx.y;
    const float* x = (which == 0) ? vals : (which == 1) ? keys : qry;
    const float* W = (which == 0) ? Wv : (which == 1) ? Wk : Wq;
    float* out = (which == 0) ? g_vp : (which == 1) ? g_kp : g_qp;

    const int bh = blockIdx.x;
    const int b = bh >> 4, h = bh & 15;

    __shared__ float Ws[Dcst][Dcst];   // Ws[j][d] = W[d][j]  (float4 over d)
    __shared__ float Xs[16][Dcst];

    const int tid = threadIdx.x;
    for (int i = tid; i < Dcst * Dcst; i += 256) {
        int d = i >> 6, j = i & 63;
        Ws[j][d] = W[i];
    }
    __syncthreads();

    const int d4 = tid & 15;       // handles d = d4*4 .. d4*4+3
    const int r  = tid >> 4;       // row within 16-row chunk
    const size_t xbase = (size_t)b * Lcst * Ecst + (size_t)h * Dcst;

    for (int l0 = 0; l0 < Lcst; l0 += 16) {
        *(float4*)&Xs[r][d4 * 4] =
            *(const float4*)&x[xbase + (size_t)(l0 + r) * Ecst + d4 * 4];
        __syncthreads();

        float4 acc = make_float4(0.f, 0.f, 0.f, 0.f);
#pragma unroll
        for (int j = 0; j < Dcst; j++) {
            float xv = Xs[r][j];
            float4 w = *(const float4*)&Ws[j][d4 * 4];
            acc.x += xv * w.x; acc.y += xv * w.y;
            acc.z += xv * w.z; acc.w += xv * w.w;
        }
        *(float4*)&out[((size_t)bh * Lcst + l0 + r) * Dcst + d4 * 4] = acc;
        __syncthreads();
    }
}

// ---------------------------------------------------------------------------
// Kernel 2: S^T[bh][k][q] = (K[k] . Q[q]) * 1/sqrt(512), masked on q.
// 128x128 tile, BK=32, 8x8 micro-tile, 256 threads. grid (4,4,256).
// ---------------------------------------------------------------------------
__global__ __launch_bounds__(256) void qk_kernel(const int* __restrict__ mask)
{
    const int bh = blockIdx.z;
    const int b = bh >> 4;
    const int k0 = blockIdx.y * 128;   // key rows (M)
    const int q0 = blockIdx.x * 128;   // query cols (N)

    __shared__ float As[32][132];      // As[j][k-row]
    __shared__ float Bs[32][132];      // Bs[j][q-col]
    __shared__ float Mf[128];          // mask flag per q (1=keep, 0=mask)

    const int tid = threadIdx.x;
    const int tx = tid & 15, ty = tid >> 4;

    if (tid < 128) Mf[tid] = (mask[b * Lcst + q0 + tid] == 0) ? 0.f : 1.f;

    float c[8][8];
#pragma unroll
    for (int i = 0; i < 8; i++)
#pragma unroll
        for (int j = 0; j < 8; j++) c[i][j] = 0.f;

    const float* kbase = &g_kp[(size_t)bh * Lcst * Dcst];
    const float* qbase = &g_qp[(size_t)bh * Lcst * Dcst];

    for (int kk0 = 0; kk0 < Dcst; kk0 += 32) {
#pragma unroll
        for (int it = 0; it < 4; it++) {
            int idx = tid + it * 256;          // 1024 float4s (128 rows x 8)
            int row = idx >> 3, c4 = idx & 7;
            float4 va = *(const float4*)&kbase[(size_t)(k0 + row) * Dcst + kk0 + c4 * 4];
            As[c4 * 4 + 0][row] = va.x; As[c4 * 4 + 1][row] = va.y;
            As[c4 * 4 + 2][row] = va.z; As[c4 * 4 + 3][row] = va.w;
            float4 vb = *(const float4*)&qbase[(size_t)(q0 + row) * Dcst + kk0 + c4 * 4];
            Bs[c4 * 4 + 0][row] = vb.x; Bs[c4 * 4 + 1][row] = vb.y;
            Bs[c4 * 4 + 2][row] = vb.z; Bs[c4 * 4 + 3][row] = vb.w;
        }
        __syncthreads();
#pragma unroll
        for (int kj = 0; kj < 32; kj++) {
            float a[8], bb[8];
            *(float4*)&a[0] = *(const float4*)&As[kj][ty * 8];
            *(float4*)&a[4] = *(const float4*)&As[kj][ty * 8 + 4];
            *(float4*)&bb[0] = *(const float4*)&Bs[kj][tx * 8];
            *(float4*)&bb[4] = *(const float4*)&Bs[kj][tx * 8 + 4];
#pragma unroll
            for (int i = 0; i < 8; i++)
#pragma unroll
                for (int j = 0; j < 8; j++) c[i][j] += a[i] * bb[j];
        }
        __syncthreads();
    }

    const float scale = 0.044194173824159216f;   // 1/sqrt(512)
    const size_t base = (size_t)bh * Lcst * Lcst;
#pragma unroll
    for (int i = 0; i < 8; i++) {
        int kr = k0 + ty * 8 + i;
#pragma unroll
        for (int j4 = 0; j4 < 2; j4++) {
            int qj = tx * 8 + j4 * 4;
            float4 r;
            r.x = (Mf[qj + 0] == 0.f) ? -1e30f : c[i][j4 * 4 + 0] * scale;
            r.y = (Mf[qj + 1] == 0.f) ? -1e30f : c[i][j4 * 4 + 1] * scale;
            r.z = (Mf[qj + 2] == 0.f) ? -1e30f : c[i][j4 * 4 + 2] * scale;
            r.w = (Mf[qj + 3] == 0.f) ? -1e30f : c[i][j4 * 4 + 3] * scale;
            *(float4*)&g_st[base + (size_t)kr * Lcst + q0 + qj] = r;
        }
    }
}

// ---------------------------------------------------------------------------
// Kernel 3: per (bh,k) row of S^T, reduce over the 512 q values: max, 1/sum.
// One warp per row. grid 16384, block 256 (8 warps).
// ---------------------------------------------------------------------------
__global__ __launch_bounds__(256) void colstat_kernel()
{
    const int gw = blockIdx.x * 8 + (threadIdx.x >> 5);   // flattened (bh*512 + k)
    const int lane = threadIdx.x & 31;
    const float* row = &g_st[(size_t)gw * Lcst];

    float4 v[4];
    float m = -1e38f;
#pragma unroll
    for (int i = 0; i < 4; i++) {
        v[i] = *(const float4*)&row[(i * 32 + lane) * 4];
        m = fmaxf(m, fmaxf(fmaxf(v[i].x, v[i].y), fmaxf(v[i].z, v[i].w)));
    }
#pragma unroll
    for (int o = 16; o > 0; o >>= 1) m = fmaxf(m, __shfl_xor_sync(0xffffffffu, m, o));

    float s = 0.f;
#pragma unroll
    for (int i = 0; i < 4; i++) {
        s += __expf(v[i].x - m) + __expf(v[i].y - m) +
             __expf(v[i].z - m) + __expf(v[i].w - m);
    }
#pragma unroll
    for (int o = 16; o > 0; o >>= 1) s += __shfl_xor_sync(0xffffffffu, s, o);

    if (lane == 0) { g_cm[gw] = m; g_ci[gw] = 1.f / s; }
}

// ---------------------------------------------------------------------------
// Kernel 4: Out[q][d] = sum_k exp(S^T[k][q]-m[k])*invZ[k] * V[k][d]
// exp fused into the P-tile load. 128(q) x 64(d) tile, BK=32, 8x4 micro.
// grid (4, 256), block 256.
// ---------------------------------------------------------------------------
__global__ __launch_bounds__(256) void av_kernel()
{
    const int bh = blockIdx.y;
    const int b = bh >> 4, h = bh & 15;
    const int q0 = blockIdx.x * 128;

    __shared__ float Ps[32][132];   // Ps[kj][q]
    __shared__ float Vs[32][68];    // Vs[kj][d]

    const int tid = threadIdx.x;
    const int tx = tid & 15, ty = tid >> 4;

    float c[8][4];
#pragma unroll
    for (int i = 0; i < 8; i++)
#pragma unroll
        for (int j = 0; j < 4; j++) c[i][j] = 0.f;

    const float* stbase = &g_st[(size_t)bh * Lcst * Lcst];
    const float* vbase  = &g_vp[(size_t)bh * Lcst * Dcst];

    for (int kc = 0; kc < Lcst; kc += 32) {
#pragma unroll
        for (int it = 0; it < 4; it++) {
            int idx = tid + it * 256;            // 1024 float4s (32 rows x 32)
            int kr = idx >> 5, q4 = idx & 31;
            int kg = kc + kr;
            float mv = g_cm[bh * Lcst + kg];
            float iz = g_ci[bh * Lcst + kg];
            float4 v = *(const float4*)&stbase[(size_t)kg * Lcst + q0 + q4 * 4];
            float4 p;
            p.x = __expf(v.x - mv) * iz;
            p.y = __expf(v.y - mv) * iz;
            p.z = __expf(v.z - mv) * iz;
            p.w = __expf(v.w - mv) * iz;
            *(float4*)&Ps[kr][q4 * 4] = p;
        }
#pragma unroll
        for (int it = 0; it < 2; it++) {
            int idx = tid + it * 256;            // 512 float4s (32 rows x 16)
            int kr = idx >> 4, d4 = idx & 15;
            *(float4*)&Vs[kr][d4 * 4] =
                *(const float4*)&vbase[(size_t)(kc + kr) * Dcst + d4 * 4];
        }
        __syncthreads();
#pragma unroll
        for (int kj = 0; kj < 32; kj++) {
            float a[8], bb[4];
            *(float4*)&a[0] = *(const float4*)&Ps[kj][ty * 8];
            *(float4*)&a[4] = *(const float4*)&Ps[kj][ty * 8 + 4];
            *(float4*)&bb[0] = *(const float4*)&Vs[kj][tx * 4];
#pragma unroll
            for (int i = 0; i < 8; i++)
#pragma unroll
                for (int j = 0; j < 4; j++) c[i][j] += a[i] * bb[j];
        }
        __syncthreads();
    }

#pragma unroll
    for (int i = 0; i < 8; i++) {
        int q = q0 + ty * 8 + i;
        *(float4*)&g_att[((size_t)(b * Lcst + q)) * Ecst + h * Dcst + tx * 4] =
            make_float4(c[i][0], c[i][1], c[i][2], c[i][3]);
    }
}

// ---------------------------------------------------------------------------
// Kernel 5: out[t][i] = sum_j g_att[t][j] * Wo[i][j] + bo[i]
// 128x128x16 tiles, 8x8 micro. grid (64, 8), block 256.
// ---------------------------------------------------------------------------
__global__ __launch_bounds__(256) void out_gemm(const float* __restrict__ Wo,
                                                const float* __restrict__ bo,
                                                float* __restrict__ out)
{
    const int m0 = blockIdx.x * 128;
    const int n0 = blockIdx.y * 128;

    __shared__ float As[16][132];
    __shared__ float Bs[16][132];

    const int tid = threadIdx.x;
    const int tx = tid & 15, ty = tid >> 4;

    float c[8][8];
#pragma unroll
    for (int i = 0; i < 8; i++)
#pragma unroll
        for (int j = 0; j < 8; j++) c[i][j] = 0.f;

    for (int k0 = 0; k0 < Ecst; k0 += 16) {
#pragma unroll
        for (int it = 0; it < 2; it++) {
            int idx = tid + it * 256;        // 512 float4s (128 rows x 4)
            int row = idx >> 2, c4 = idx & 3;
            float4 va = *(const float4*)&g_att[(size_t)(m0 + row) * Ecst + k0 + c4 * 4];
            As[c4 * 4 + 0][row] = va.x; As[c4 * 4 + 1][row] = va.y;
            As[c4 * 4 + 2][row] = va.z; As[c4 * 4 + 3][row] = va.w;
            float4 vb = *(const float4*)&Wo[(size_t)(n0 + row) * Ecst + k0 + c4 * 4];
            Bs[c4 * 4 + 0][row] = vb.x; Bs[c4 * 4 + 1][row] = vb.y;
            Bs[c4 * 4 + 2][row] = vb.z; Bs[c4 * 4 + 3][row] = vb.w;
        }
        __syncthreads();
#pragma unroll
        for (int kj = 0; kj < 16; kj++) {
            float a[8], bb[8];
            *(float4*)&a[0] = *(const float4*)&As[kj][ty * 8];
            *(float4*)&a[4] = *(const float4*)&As[kj][ty * 8 + 4];
            *(float4*)&bb[0] = *(const float4*)&Bs[kj][tx * 8];
            *(float4*)&bb[4] = *(const float4*)&Bs[kj][tx * 8 + 4];
#pragma unroll
            for (int i = 0; i < 8; i++)
#pragma unroll
                for (int j = 0; j < 8; j++) c[i][j] += a[i] * bb[j];
        }
        __syncthreads();
    }

#pragma unroll
    for (int i = 0; i < 8; i++) {
        int m = m0 + ty * 8 + i;
#pragma unroll
        for (int j4 = 0; j4 < 2; j4++) {
            int n = n0 + tx * 8 + j4 * 4;
            float4 r;
            r.x = c[i][j4 * 4 + 0] + bo[n + 0];
            r.y = c[i][j4 * 4 + 1] + bo[n + 1];
            r.z = c[i][j4 * 4 + 2] + bo[n + 2];
            r.w = c[i][j4 * 4 + 3] + bo[n + 3];
            *(float4*)&out[(size_t)m * Ecst + n] = r;
        }
    }
}

// ---------------------------------------------------------------------------
extern "C" void kernel_launch(void* const* d_in, const int* in_sizes, int n_in,
                              void* d_out, int out_size)
{
    const float* vals = (const float*)d_in[0];
    const float* keys = (const float*)d_in[1];
    const float* qry  = (const float*)d_in[2];
    const int*   mask = (const int*)d_in[3];
    const float* Wv   = (const float*)d_in[4];
    const float* Wk   = (const float*)d_in[5];
    const float* Wq   = (const float*)d_in[6];
    const float* Wo   = (const float*)d_in[7];
    const float* bo   = (const float*)d_in[8];
    float* out = (float*)d_out;

    proj_kernel<<<dim3(BHcst, 3), 256>>>(vals, keys, qry, Wv, Wk, Wq);
    qk_kernel<<<dim3(4, 4, BHcst), 256>>>(mask);
    colstat_kernel<<<BHcst * Lcst / 8, 256>>>();
    av_kernel<<<dim3(4, BHcst), 256>>>();
    out_gemm<<<dim3(Tcst / 128, Ecst / 128), 256>>>(Wo, bo, out);
}